// round 5
// baseline (speedup 1.0000x reference)
#include <cuda_runtime.h>
#include <math.h>

#define NROWS   2048
#define DIM     256
#define SLEN    1024
#define TOUT    512
#define NBATCH  2
#define LSTRIDE 512
#define LN_EPS  1e-5f
#define TWOPI_F 6.283185307179586f
#define SGNMASK2 0x8000000080000000ULL

typedef unsigned long long ull;

// Packed fp32x2 helpers (Blackwell sm_100+): one issue slot = 2 IEEE fp32 FMAs
#define PACKF2(p, lo, hi) asm("mov.b64 %0, {%1, %2};" : "=l"(p) : "f"(lo), "f"(hi))
#define UNPACKF2(lo, hi, p) asm("mov.b64 {%0, %1}, %2;" : "=f"(lo), "=f"(hi) : "l"(p))
#define FMAF2(d, a, b, c) asm("fma.rn.f32x2 %0, %1, %2, %3;" : "=l"(d) : "l"(a), "l"(b), "l"(c))

// Scratch (allocation-free rule: __device__ globals)
__device__ float  g_Y[NROWS * DIM];
__device__ float  g_Z[NROWS * DIM];
__device__ float  g_R[NROWS * DIM];
__device__ float4 g_Par4[DIM * DIM];                 // {P, 1/p, p, +2cos(4pi/p)}
__device__ float  g_Tpart[8][NROWS * DIM];           // split-j partials of T
__device__ float  g_TR[NROWS * DIM * 2];             // interleaved {T, R} pairs
__device__ float  g_part[8][NBATCH * TOUT * DIM];    // linker split-K partials

// ---------------------------------------------------------------------------
// K0: per-(i,j) parameter table. Recurrence coeff computed in fp64.
// ---------------------------------------------------------------------------
__global__ __launch_bounds__(256) void param4_kernel(const float* __restrict__ P)
{
    int idx = blockIdx.x * 256 + threadIdx.x;        // i*256+j
    int pidx = idx + 2;                              // p = i*256+j+2
    float pf = (float)pidx;
    float ip = 1.0f / pf;
    float c2p = (float)(2.0 * cos(12.566370614359172 / (double)pidx)); // +2cos(4pi/p)
    float4 v; v.x = P[idx]; v.y = ip; v.z = pf; v.w = c2p;
    g_Par4[idx] = v;
}

// ---------------------------------------------------------------------------
// K1: fused dual GEMM: Y = x@M^T, R = x@resW^T  (shared x tiles)
// ---------------------------------------------------------------------------
__global__ __launch_bounds__(128) void dual_gemm_kernel(
    const float* __restrict__ x, const float* __restrict__ Mw,
    const float* __restrict__ Rw)
{
    __shared__ float As[16][36];
    __shared__ float B1[16][68];
    __shared__ float B2[16][68];

    const int tid = threadIdx.x;
    const int tx = tid & 15;
    const int ty = tid >> 4;
    const int m0 = blockIdx.y * 32;
    const int n0 = blockIdx.x * 64;

    float aY[4][4] = {}, aR[4][4] = {};

    for (int k0 = 0; k0 < DIM; k0 += 16) {
#pragma unroll
        for (int l = 0; l < 4; l++) {
            int e = tid + l * 128; int r = e >> 4, c = e & 15;
            As[c][r] = x[(m0 + r) * DIM + k0 + c];
        }
#pragma unroll
        for (int l = 0; l < 8; l++) {
            int e = tid + l * 128; int r = e >> 4, c = e & 15;
            B1[c][r] = Mw[(n0 + r) * DIM + k0 + c];
            B2[c][r] = Rw[(n0 + r) * DIM + k0 + c];
        }
        __syncthreads();
#pragma unroll
        for (int kk = 0; kk < 16; kk++) {
            float4 av = *(const float4*)&As[kk][ty * 4];
            float4 b1 = *(const float4*)&B1[kk][tx * 4];
            float4 b2 = *(const float4*)&B2[kk][tx * 4];
            float a[4]  = {av.x, av.y, av.z, av.w};
            float v1[4] = {b1.x, b1.y, b1.z, b1.w};
            float v2[4] = {b2.x, b2.y, b2.z, b2.w};
#pragma unroll
            for (int i = 0; i < 4; i++)
#pragma unroll
                for (int j = 0; j < 4; j++) {
                    aY[i][j] = fmaf(a[i], v1[j], aY[i][j]);
                    aR[i][j] = fmaf(a[i], v2[j], aR[i][j]);
                }
        }
        __syncthreads();
    }

#pragma unroll
    for (int i = 0; i < 4; i++) {
        float4 vy = {aY[i][0], aY[i][1], aY[i][2], aY[i][3]};
        float4 vr = {aR[i][0], aR[i][1], aR[i][2], aR[i][3]};
        int row = m0 + ty * 4 + i;
        *(float4*)&g_Y[row * DIM + n0 + tx * 4] = vy;
        *(float4*)&g_R[row * DIM + n0 + tx * 4] = vr;
    }
}

// ---------------------------------------------------------------------------
// K2: LayerNorm rows of g_Y -> g_Z.  One warp per row.
// ---------------------------------------------------------------------------
__global__ __launch_bounds__(256) void ln_kernel(
    const float* __restrict__ gamma, const float* __restrict__ beta)
{
    const int warp = threadIdx.x >> 5;
    const int lane = threadIdx.x & 31;
    const int row  = blockIdx.x * 8 + warp;
    const float* y = g_Y + row * DIM;

    float v[8];
    float s = 0.f;
#pragma unroll
    for (int l = 0; l < 8; l++) { v[l] = y[lane + l * 32]; s += v[l]; }
#pragma unroll
    for (int o = 16; o > 0; o >>= 1) s += __shfl_xor_sync(0xffffffffu, s, o);
    const float mu = s * (1.0f / DIM);

    float s2 = 0.f;
#pragma unroll
    for (int l = 0; l < 8; l++) { float d = v[l] - mu; s2 = fmaf(d, d, s2); }
#pragma unroll
    for (int o = 16; o > 0; o >>= 1) s2 += __shfl_xor_sync(0xffffffffu, s2, o);
    const float inv = rsqrtf(s2 * (1.0f / DIM) + LN_EPS);

#pragma unroll
    for (int l = 0; l < 8; l++) {
        int c = lane + l * 32;
        g_Z[row * DIM + c] = (v[l] - mu) * inv * gamma[c] + beta[c];
    }
}

// ---------------------------------------------------------------------------
// K3: T[k,i] = sum_j Z[k,j] * P[i,j] * cos(2*pi*k / p_ij)
// 32 consecutive k per thread via step-2 Chebyshev pair recurrence (f32x2):
//   D_m = {d_2m, d_2m+1},  D_{m+1} = 2cos(2delta)*D_m - D_{m-1}
// The "- D_{m-1}" is kept EXACT by carrying the negated previous value,
// refreshed with a packed sign-bit XOR (alu pipe, overlaps fma stream).
// Seeds (4 MUFU cos) via exact integer mod reduction.
// Block: 128 thr = 4 warps; warp w owns k-group of 32; lanes = 32 i.
// Tile: 128k x 32i x 32j; grid (8, 16, 8 j-splits) = 1024 blocks.
// ---------------------------------------------------------------------------
__global__ __launch_bounds__(128) void tphi_kernel()
{
    __shared__ __align__(16) float  Zs[32][134];   // [j][k], padded
    __shared__ __align__(16) float4 Pw[32][33];    // [j][i] params

    const int tid = threadIdx.x;
    const int tx  = tid & 31;       // i lane
    const int w   = tid >> 5;       // k-group
    const int i0  = blockIdx.x * 32;
    const int k0  = blockIdx.y * 128;
    const int jc  = blockIdx.z * 32;

#pragma unroll
    for (int l = 0; l < 32; l++) {                 // Z tile 128k x 32j (transposed)
        int e = tid + l * 128; int r = e >> 5, c = e & 31;
        Zs[c][r] = g_Z[(k0 + r) * DIM + jc + c];
    }
#pragma unroll
    for (int l = 0; l < 8; l++) {                  // param tile 32i x 32j
        int e = tid + l * 128; int jj = e & 31, il = e >> 5;
        Pw[jj][il] = g_Par4[(i0 + il) * DIM + jc + jj];
    }
    __syncthreads();

    const float kf0 = (float)(k0 + w * 32);
    ull acc[16];
#pragma unroll
    for (int m = 0; m < 16; m++) acc[m] = 0ull;

#pragma unroll 4
    for (int jj = 0; jj < 32; jj++) {
        float4 pr = Pw[jj][tx];                    // {P, 1/p, p, 2cos(4pi/p)}
        const ull* zp = (const ull*)&Zs[jj][w * 32];

        float tw = TWOPI_F * pr.y;
        float u  = kf0 * pr.y;
        float q  = rintf(u);
        float km = fmaf(-pr.z, q, kf0);            // exact k mod p (up to +-p)
        float t0 = km * tw;
        float t1 = t0 + tw;
        float t2 = t1 + tw;
        float t3 = t2 + tw;
        float c0 = __cosf(t0), c1 = __cosf(t1), c2 = __cosf(t2), c3 = __cosf(t3);

        ull D0, D1, C;
        PACKF2(D0, pr.x * c0, pr.x * c1);          // D0 = {d0, d1}
        PACKF2(D1, pr.x * c2, pr.x * c3);          // D1 = {d2, d3}
        PACKF2(C,  pr.w,      pr.w);               // 2cos(2*delta)

        FMAF2(acc[0], zp[0], D0, acc[0]);
        FMAF2(acc[1], zp[1], D1, acc[1]);
        ull EpN = D0 ^ SGNMASK2;                   // -D_{m-1}
        ull Ec  = D1;                              //  D_m
#pragma unroll
        for (int m = 2; m < 16; m++) {
            ull Dn; FMAF2(Dn, C, Ec, EpN);         // D_{m+1} = 2c*D_m - D_{m-1}
            FMAF2(acc[m], zp[m], Dn, acc[m]);
            EpN = Ec ^ SGNMASK2;
            Ec  = Dn;
        }
    }

    float* dst = g_Tpart[blockIdx.z];
#pragma unroll
    for (int m = 0; m < 16; m++) {
        float lo, hi; UNPACKF2(lo, hi, acc[m]);
        int k = k0 + w * 32 + 2 * m;
        dst[k * DIM + i0 + tx]       = lo;
        dst[(k + 1) * DIM + i0 + tx] = hi;
    }
}

// ---------------------------------------------------------------------------
// K3b: reduce 8 j-split partials of T and interleave with R -> g_TR {T,R} pairs
// ---------------------------------------------------------------------------
__global__ __launch_bounds__(256) void treduce_kernel()
{
    int idx = blockIdx.x * 256 + threadIdx.x;      // 0..524287 = k*256+i
    float s = ((g_Tpart[0][idx] + g_Tpart[1][idx]) + (g_Tpart[2][idx] + g_Tpart[3][idx]))
            + ((g_Tpart[4][idx] + g_Tpart[5][idx]) + (g_Tpart[6][idx] + g_Tpart[7][idx]));
    float2 v; v.x = s; v.y = g_R[idx];
    ((float2*)g_TR)[idx] = v;
}

// ---------------------------------------------------------------------------
// K4: split-K linker, packed f32x2. Pairs {L,rL} x {T,R} advance both GEMMs
// per FMA lane-wise; halves summed at epilogue.
// tile 64t x 64d, 256 thr, split-K=8 (128 s each); grid (4,8,16) = 512 blocks
// ---------------------------------------------------------------------------
__global__ __launch_bounds__(256) void linker_kernel(
    const float* __restrict__ L, const float* __restrict__ rL)
{
    __shared__ __align__(16) float LGs[32][132];   // {L,rL} interleaved, 64 t
    __shared__ __align__(16) float TRs[32][132];   // {T,R}  interleaved, 64 d

    const int tid = threadIdx.x;
    const int tx = tid & 15;     // d micro
    const int ty = tid >> 4;     // t micro
    const int b     = blockIdx.z >> 3;
    const int split = blockIdx.z & 7;
    const int t0 = blockIdx.y * 64;
    const int d0 = blockIdx.x * 64;
    const int sbase = split * 128;

    ull acc[4][4];
#pragma unroll
    for (int i = 0; i < 4; i++)
#pragma unroll
        for (int j = 0; j < 4; j++) acc[i][j] = 0ull;

    for (int s0 = sbase; s0 < sbase + 128; s0 += 32) {
#pragma unroll
        for (int l = 0; l < 2; l++) {              // LG fill: interleave L/rL
            int e = tid + l * 256;                 // 0..511, 4 t's each
            int sr = e >> 4, tq = (e & 15) * 4;
            float4 a = *(const float4*)&L [(s0 + sr) * LSTRIDE + t0 + tq];
            float4 g = *(const float4*)&rL[(s0 + sr) * LSTRIDE + t0 + tq];
            float4 u0 = {a.x, g.x, a.y, g.y};
            float4 u1 = {a.z, g.z, a.w, g.w};
            *(float4*)&LGs[sr][2 * tq]     = u0;
            *(float4*)&LGs[sr][2 * tq + 4] = u1;
        }
#pragma unroll
        for (int l = 0; l < 4; l++) {              // TR fill: straight copy
            int e = tid + l * 256;                 // 0..1023
            int sr = e >> 5, c4 = (e & 31) * 4;
            *(float4*)&TRs[sr][c4] =
                *(const float4*)&g_TR[((b << 10) + s0 + sr) * (2 * DIM) + 2 * d0 + c4];
        }
        __syncthreads();
#pragma unroll 8
        for (int kk = 0; kk < 32; kk++) {
            longlong2 A0 = *(const longlong2*)&LGs[kk][ty * 8];
            longlong2 A1 = *(const longlong2*)&LGs[kk][ty * 8 + 4];
            longlong2 B0 = *(const longlong2*)&TRs[kk][tx * 8];
            longlong2 B1 = *(const longlong2*)&TRs[kk][tx * 8 + 4];
            ull Ap[4] = {(ull)A0.x, (ull)A0.y, (ull)A1.x, (ull)A1.y};
            ull Bp[4] = {(ull)B0.x, (ull)B0.y, (ull)B1.x, (ull)B1.y};
#pragma unroll
            for (int i = 0; i < 4; i++)
#pragma unroll
                for (int j = 0; j < 4; j++)
                    FMAF2(acc[i][j], Ap[i], Bp[j], acc[i][j]);
        }
        __syncthreads();
    }

    float* dst = g_part[split];
#pragma unroll
    for (int i = 0; i < 4; i++) {
        float r[4];
#pragma unroll
        for (int j = 0; j < 4; j++) {
            float lo, hi; UNPACKF2(lo, hi, acc[i][j]);
            r[j] = lo + hi;                        // T-part + R-part
        }
        float4 v = {r[0], r[1], r[2], r[3]};
        *(float4*)&dst[(b * TOUT + t0 + ty * 4 + i) * DIM + d0 + tx * 4] = v;
    }
}

// ---------------------------------------------------------------------------
// K5: deterministic split-K reduction (8 partials)
// ---------------------------------------------------------------------------
__global__ __launch_bounds__(256) void reduce_kernel(float* __restrict__ out)
{
    int idx = blockIdx.x * 256 + threadIdx.x;      // float4 index, 65536 total
    float4 s = {0.f, 0.f, 0.f, 0.f};
#pragma unroll
    for (int p = 0; p < 8; p++) {
        float4 v = ((const float4*)g_part[p])[idx];
        s.x += v.x; s.y += v.y; s.z += v.z; s.w += v.w;
    }
    ((float4*)out)[idx] = s;
}

// ---------------------------------------------------------------------------
extern "C" void kernel_launch(void* const* d_in, const int* in_sizes, int n_in,
                              void* d_out, int out_size)
{
    const float* x       = (const float*)d_in[0];
    const float* Mw      = (const float*)d_in[1];
    const float* P       = (const float*)d_in[2];
    const float* Linker  = (const float*)d_in[3];
    const float* gamma   = (const float*)d_in[4];
    const float* beta    = (const float*)d_in[5];
    const float* resW    = (const float*)d_in[6];
    const float* rLinker = (const float*)d_in[7];
    float* out = (float*)d_out;

    param4_kernel<<<DIM * DIM / 256, 256>>>(P);

    dim3 g1(DIM / 64, NROWS / 32);
    dual_gemm_kernel<<<g1, 128>>>(x, Mw, resW);

    ln_kernel<<<NROWS / 8, 256>>>(gamma, beta);

    dim3 g3(DIM / 32, NROWS / 128, 8);
    tphi_kernel<<<g3, 128>>>();

    treduce_kernel<<<NROWS * DIM / 256, 256>>>();

    dim3 g4(DIM / 64, TOUT / 64, NBATCH * 8);
    linker_kernel<<<g4, 256>>>(Linker, rLinker);

    reduce_kernel<<<NBATCH * TOUT * DIM / 4 / 256, 256>>>(out);
}